// round 16
// baseline (speedup 1.0000x reference)
#include <cuda_runtime.h>
#include <cuda_fp16.h>
#include <cstdint>
#include <cstring>

// O[n,m] = sum_k softmax(S)[n,k] * V[m,k],  D=256, n=m=8192.
// mma.sync m16n8k16 fp16 f32-acc, fragment-major fp16 scratch, persistent
// CTAs, K chunks of 128 (2 per tile), 2-stage x 96KB cp.async pipeline.
// gemm is at the legacy-HMMA 16-cyc dispatch floor; prep fully vectorized.

#define DK 256
#define BM 128
#define BN 256
#define THREADS 256
#define NTILES (32 * 64)
#define GRID_P 148

#define A_BYTES (BM * 128 * 2) /* 32768 */
#define B_BYTES (BN * 128 * 2) /* 65536 */
#define STG_BYTES (A_BYTES + B_BYTES) /* 98304 */
#define SMEM_TOTAL (2 * STG_BYTES)    /* 196608 */
#define SROW 264

__device__ __half g_Ph[8192 * DK];
__device__ __half g_Vh[8192 * DK];

__device__ __forceinline__ uint32_t h2u(__half2 h) {
    uint32_t u;
    memcpy(&u, &h, 4);
    return u;
}
__device__ __forceinline__ uint32_t smem_u32(const void* p) {
    uint32_t a;
    asm("{ .reg .u64 t; cvta.to.shared.u64 t, %1; cvt.u32.u64 %0, t; }"
        : "=r"(a) : "l"(p));
    return a;
}
__device__ __forceinline__ void cp16(uint32_t dst, const void* src) {
    asm volatile("cp.async.cg.shared.global [%0], [%1], 16;" :: "r"(dst), "l"(src)
                 : "memory");
}
__device__ __forceinline__ void lds128(uint32_t* d, uint32_t addr) {
    asm volatile("ld.shared.v4.b32 {%0,%1,%2,%3}, [%4];"
                 : "=r"(d[0]), "=r"(d[1]), "=r"(d[2]), "=r"(d[3]) : "r"(addr));
}
__device__ __forceinline__ void mma_fp16(float* d, const uint32_t* a,
                                         uint32_t b0, uint32_t b1) {
    asm volatile(
        "mma.sync.aligned.m16n8k16.row.col.f32.f16.f16.f32 "
        "{%0,%1,%2,%3}, {%4,%5,%6,%7}, {%8,%9}, {%0,%1,%2,%3};"
        : "+f"(d[0]), "+f"(d[1]), "+f"(d[2]), "+f"(d[3])
        : "r"(a[0]), "r"(a[1]), "r"(a[2]), "r"(a[3]), "r"(b0), "r"(b1));
}

// Fragment-major index (fp16 elems) for A scratch, element (r, k):
// [tile128][kc2][wrow2][mt4][ks8][lane32][q4][e2]; q = hk*2 + h8
__device__ __forceinline__ size_t idxA(int r, int k) {
    int tile = r >> 7, wrow = (r >> 6) & 1, mt = (r >> 4) & 3;
    int h8 = (r >> 3) & 1, g = r & 7;
    int kc = k >> 7, ks = (k >> 4) & 7, kk = k & 15;
    int hk = kk >> 3, t = (kk >> 1) & 3, e = kk & 1;
    int lane = g * 4 + t;
    int q = hk * 2 + h8;
    return ((((((size_t)tile * 2 + kc) * 2 + wrow) * 4 + mt) * 8 + ks) * 32 + lane) * 8
           + q * 2 + e;
}
// Fragment-major index for B scratch, element (v, k):
// [tile256][kc2][wcol4][j4][ks8][lane32][q4][e2]; q = p*2 + hk (p=(v>>3)&1)
__device__ __forceinline__ size_t idxB(int v, int k) {
    int tile = v >> 8, wcol = (v >> 6) & 3, j = (v >> 4) & 3;
    int p = (v >> 3) & 1, g = v & 7;
    int kc = k >> 7, ks = (k >> 4) & 7, kk = k & 15;
    int hk = kk >> 3, t = (kk >> 1) & 3, e = kk & 1;
    int lane = g * 4 + t;
    int q = p * 2 + hk;
    return ((((((size_t)tile * 2 + kc) * 4 + wcol) * 4 + j) * 8 + ks) * 32 + lane) * 8
           + q * 2 + e;
}

// ---- prep: blocks 0..511 softmax (16 rows each), 512..767 V convert -------
__global__ void __launch_bounds__(512, 1) prep_k(const float* __restrict__ S,
                                                 const float* __restrict__ V) {
    if (blockIdx.x < 512) {
        __shared__ __half sm[16 * SROW];
        int base = blockIdx.x * 16;
        int w = threadIdx.x >> 5, lane = threadIdx.x & 31;
        int row = base + w;
        const float4* Sr = reinterpret_cast<const float4*>(S + (size_t)row * DK);
        float4 v0 = Sr[lane * 2];
        float4 v1 = Sr[lane * 2 + 1];
        float e[8] = {v0.x, v0.y, v0.z, v0.w, v1.x, v1.y, v1.z, v1.w};
        float mx = e[0];
#pragma unroll
        for (int i = 1; i < 8; i++) mx = fmaxf(mx, e[i]);
#pragma unroll
        for (int o = 16; o; o >>= 1) mx = fmaxf(mx, __shfl_xor_sync(0xffffffffu, mx, o));
        float s = 0.0f;
#pragma unroll
        for (int i = 0; i < 8; i++) { e[i] = __expf(e[i] - mx); s += e[i]; }
#pragma unroll
        for (int o = 16; o; o >>= 1) s += __shfl_xor_sync(0xffffffffu, s, o);
        float inv = __frcp_rn(s);
        uint32_t h01 = h2u(__floats2half2_rn(e[0] * inv, e[1] * inv));
        uint32_t h23 = h2u(__floats2half2_rn(e[2] * inv, e[3] * inv));
        uint32_t h45 = h2u(__floats2half2_rn(e[4] * inv, e[5] * inv));
        uint32_t h67 = h2u(__floats2half2_rn(e[6] * inv, e[7] * inv));
        uint32_t sb = smem_u32(sm);
        asm volatile("st.shared.v4.b32 [%0], {%1,%2,%3,%4};"
                     :: "r"(sb + (uint32_t)(w * SROW + lane * 8) * 2),
                        "r"(h01), "r"(h23), "r"(h45), "r"(h67));
        __syncthreads();
        // phase 2: 512 chunks = kc2 x ks8 x lane32; one 16B v4 store each
        int c = threadIdx.x;
        int l = c & 31, ks = (c >> 5) & 7, kc = (c >> 8) & 1;
        int g = l >> 2, t4 = l & 3;
        int k0 = kc * 128 + ks * 16 + 2 * t4;
        const __half2* a0 = reinterpret_cast<const __half2*>(sm + g * SROW);
        const __half2* a8 = reinterpret_cast<const __half2*>(sm + (g + 8) * SROW);
        uint4 outv = make_uint4(h2u(a0[k0 >> 1]), h2u(a8[k0 >> 1]),
                                h2u(a0[(k0 >> 1) + 4]), h2u(a8[(k0 >> 1) + 4]));
        *reinterpret_cast<uint4*>(&g_Ph[idxA(base + g, k0)]) = outv;
    } else {
        // V convert: each thread builds TWO adjacent chunks from 4 float4
        // reads and 2 contiguous 16B stores. 131072 pair-units total.
        int u = (blockIdx.x - 512) * 512 + threadIdx.x;
        int t2 = u & 1, g = (u >> 1) & 7, ks = (u >> 4) & 7;
        int j = (u >> 7) & 3, wc = (u >> 9) & 3, kc = (u >> 11) & 1;
        int tile = u >> 12;
        int v0 = tile * 256 + wc * 64 + j * 16 + g;
        int kb = kc * 128 + ks * 16 + 4 * t2;
        const float4* Va = reinterpret_cast<const float4*>(V + (size_t)v0 * DK + kb);
        const float4* Vb =
            reinterpret_cast<const float4*>(V + (size_t)(v0 + 8) * DK + kb);
        float4 fa0 = Va[0];
        float4 fa8 = Va[2];
        float4 fb0 = Vb[0];
        float4 fb8 = Vb[2];
        uint4 c0 = make_uint4(h2u(__floats2half2_rn(fa0.x, fa0.y)),
                              h2u(__floats2half2_rn(fa8.x, fa8.y)),
                              h2u(__floats2half2_rn(fb0.x, fb0.y)),
                              h2u(__floats2half2_rn(fb8.x, fb8.y)));
        uint4 c1 = make_uint4(h2u(__floats2half2_rn(fa0.z, fa0.w)),
                              h2u(__floats2half2_rn(fa8.z, fa8.w)),
                              h2u(__floats2half2_rn(fb0.z, fb0.w)),
                              h2u(__floats2half2_rn(fb8.z, fb8.w)));
        uint4* dst = reinterpret_cast<uint4*>(&g_Vh[idxB(v0, kb)]);
        dst[0] = c0;
        dst[1] = c1;
    }
}

// ---------------- GEMM (R15 winner, unchanged) ------------------------------
__device__ __forceinline__ void load_stage(uint32_t sb, int s,
                                           const __half* Asrc, const __half* Bsrc,
                                           int kc, int tid) {
    uint32_t base = sb + s * STG_BYTES;
    const __half* Ak = Asrc + (size_t)kc * 16384; // 32 KB of halves
    const __half* Bk = Bsrc + (size_t)kc * 32768; // 64 KB of halves
#pragma unroll
    for (int it = 0; it < 8; it++) {
        int i = it * THREADS + tid;
        cp16(base + i * 16, Ak + i * 8);
    }
#pragma unroll
    for (int it = 0; it < 16; it++) {
        int i = it * THREADS + tid;
        cp16(base + A_BYTES + i * 16, Bk + i * 8);
    }
    asm volatile("cp.async.commit_group;" ::: "memory");
}

__global__ void __launch_bounds__(THREADS, 1)
gemm_k(float* __restrict__ out, int m) {
    extern __shared__ __half smh[];
    uint32_t sb = smem_u32(smh);
    int tid = threadIdx.x;
    int lane = tid & 31, warp = tid >> 5;
    int wrow = warp >> 2;  // 0..1 (x64 rows)
    int wcol = warp & 3;   // 0..3 (x64 cols)

    int ltile = blockIdx.x, lkc = 0, gstage = 0;
    {
        const __half* Asrc = g_Ph + (size_t)(ltile >> 5) * (2 * 16384);
        const __half* Bsrc = g_Vh + (size_t)(ltile & 31) * (2 * 32768);
        load_stage(sb, gstage, Asrc, Bsrc, lkc, tid);
        gstage ^= 1;
        if (++lkc == 2) { lkc = 0; ltile += GRID_P; }
    }

    int cstage = 0;
#pragma unroll 1
    for (int tile = blockIdx.x; tile < NTILES; tile += GRID_P) {
        float acc[4][8][4];
#pragma unroll
        for (int i = 0; i < 4; i++)
#pragma unroll
            for (int j = 0; j < 8; j++)
#pragma unroll
                for (int r = 0; r < 4; r++) acc[i][j][r] = 0.0f;

#pragma unroll 1
        for (int k = 0; k < 2; k++) {
            asm volatile("cp.async.wait_group 0;" ::: "memory");
            __syncthreads();
            if (ltile < NTILES) {
                const __half* Asrc = g_Ph + (size_t)(ltile >> 5) * (2 * 16384);
                const __half* Bsrc = g_Vh + (size_t)(ltile & 31) * (2 * 32768);
                load_stage(sb, gstage, Asrc, Bsrc, lkc, tid);
            } else {
                asm volatile("cp.async.commit_group;" ::: "memory");
            }
            gstage ^= 1;
            if (++lkc == 2) { lkc = 0; ltile += GRID_P; }

            uint32_t stage = sb + cstage * STG_BYTES;
            uint32_t aW = stage + (uint32_t)wrow * 16384 + lane * 16;
            uint32_t bW = stage + A_BYTES + (uint32_t)wcol * 16384 + lane * 16;
#pragma unroll
            for (int ks = 0; ks < 8; ks++) {
                uint32_t a[4][4], b[4][4];
#pragma unroll
                for (int mt = 0; mt < 4; mt++)
                    lds128(a[mt], aW + (uint32_t)(mt * 8 + ks) * 512);
#pragma unroll
                for (int j = 0; j < 4; j++)
                    lds128(b[j], bW + (uint32_t)(j * 8 + ks) * 512);
#pragma unroll
                for (int mt = 0; mt < 4; mt++)
#pragma unroll
                    for (int j = 0; j < 4; j++) {
                        mma_fp16(acc[mt][2 * j], a[mt], b[j][0], b[j][1]);
                        mma_fp16(acc[mt][2 * j + 1], a[mt], b[j][2], b[j][3]);
                    }
            }
            cstage ^= 1;
        }

        size_t orow0 = (size_t)(tile >> 5) * BM + wrow * 64;
        size_t ocol0 = (size_t)(tile & 31) * BN + wcol * 64;
#pragma unroll
        for (int mt = 0; mt < 4; mt++) {
#pragma unroll
            for (int nt = 0; nt < 8; nt++) {
                size_t r = orow0 + mt * 16 + (lane >> 2);
                size_t c = ocol0 + nt * 8 + (lane & 3) * 2;
                float2 v0 = make_float2(acc[mt][nt][0], acc[mt][nt][1]);
                float2 v1 = make_float2(acc[mt][nt][2], acc[mt][nt][3]);
                *reinterpret_cast<float2*>(out + r * (size_t)m + c) = v0;
                *reinterpret_cast<float2*>(out + (r + 8) * (size_t)m + c) = v1;
            }
        }
    }
}

extern "C" void kernel_launch(void* const* d_in, const int* in_sizes, int n_in,
                              void* d_out, int out_size) {
    const float* S = (const float*)d_in[0];
    const float* V = (const float*)d_in[1];
    float* out = (float*)d_out;
    int m = in_sizes[1] / DK;  // 8192 V rows

    prep_k<<<768, 512>>>(S, V);

    cudaFuncSetAttribute(gemm_k, cudaFuncAttributeMaxDynamicSharedMemorySize,
                         SMEM_TOTAL);
    gemm_k<<<GRID_P, THREADS, SMEM_TOTAL>>>(out, m);
}

// round 17
// speedup vs baseline: 1.0042x; 1.0042x over previous
#include <cuda_runtime.h>
#include <cuda_fp16.h>
#include <cstdint>
#include <cstring>

// O[n,m] = sum_k softmax(S)[n,k] * V[m,k],  D=256, n=m=8192.
// mma.sync m16n8k16 fp16 f32-acc, fragment-major fp16 scratch, persistent
// CTAs, K chunks of 128 (2 per tile), 2-stage x 96KB cp.async pipeline.
// gemm mainloop measured AT the legacy-HMMA 16-cyc dispatch floor.
// NEW: PDL (programmatic dependent launch) overlaps gemm launch/prologue
// with the prep kernel's tail; gemm grid-syncs before first scratch read.

#define DK 256
#define BM 128
#define BN 256
#define THREADS 256
#define NTILES (32 * 64)
#define GRID_P 148

#define A_BYTES (BM * 128 * 2) /* 32768 */
#define B_BYTES (BN * 128 * 2) /* 65536 */
#define STG_BYTES (A_BYTES + B_BYTES) /* 98304 */
#define SMEM_TOTAL (2 * STG_BYTES)    /* 196608 */
#define SROW 264

__device__ __half g_Ph[8192 * DK];
__device__ __half g_Vh[8192 * DK];

__device__ __forceinline__ uint32_t h2u(__half2 h) {
    uint32_t u;
    memcpy(&u, &h, 4);
    return u;
}
__device__ __forceinline__ uint32_t smem_u32(const void* p) {
    uint32_t a;
    asm("{ .reg .u64 t; cvta.to.shared.u64 t, %1; cvt.u32.u64 %0, t; }"
        : "=r"(a) : "l"(p));
    return a;
}
__device__ __forceinline__ void cp16(uint32_t dst, const void* src) {
    asm volatile("cp.async.cg.shared.global [%0], [%1], 16;" :: "r"(dst), "l"(src)
                 : "memory");
}
__device__ __forceinline__ void lds128(uint32_t* d, uint32_t addr) {
    asm volatile("ld.shared.v4.b32 {%0,%1,%2,%3}, [%4];"
                 : "=r"(d[0]), "=r"(d[1]), "=r"(d[2]), "=r"(d[3]) : "r"(addr));
}
__device__ __forceinline__ void mma_fp16(float* d, const uint32_t* a,
                                         uint32_t b0, uint32_t b1) {
    asm volatile(
        "mma.sync.aligned.m16n8k16.row.col.f32.f16.f16.f32 "
        "{%0,%1,%2,%3}, {%4,%5,%6,%7}, {%8,%9}, {%0,%1,%2,%3};"
        : "+f"(d[0]), "+f"(d[1]), "+f"(d[2]), "+f"(d[3])
        : "r"(a[0]), "r"(a[1]), "r"(a[2]), "r"(a[3]), "r"(b0), "r"(b1));
}

// Fragment-major index (fp16 elems) for A scratch, element (r, k):
// [tile128][kc2][wrow2][mt4][ks8][lane32][q4][e2]; q = hk*2 + h8
__device__ __forceinline__ size_t idxA(int r, int k) {
    int tile = r >> 7, wrow = (r >> 6) & 1, mt = (r >> 4) & 3;
    int h8 = (r >> 3) & 1, g = r & 7;
    int kc = k >> 7, ks = (k >> 4) & 7, kk = k & 15;
    int hk = kk >> 3, t = (kk >> 1) & 3, e = kk & 1;
    int lane = g * 4 + t;
    int q = hk * 2 + h8;
    return ((((((size_t)tile * 2 + kc) * 2 + wrow) * 4 + mt) * 8 + ks) * 32 + lane) * 8
           + q * 2 + e;
}
// Fragment-major index for B scratch, element (v, k):
// [tile256][kc2][wcol4][j4][ks8][lane32][q4][e2]; q = p*2 + hk (p=(v>>3)&1)
__device__ __forceinline__ size_t idxB(int v, int k) {
    int tile = v >> 8, wcol = (v >> 6) & 3, j = (v >> 4) & 3;
    int p = (v >> 3) & 1, g = v & 7;
    int kc = k >> 7, ks = (k >> 4) & 7, kk = k & 15;
    int hk = kk >> 3, t = (kk >> 1) & 3, e = kk & 1;
    int lane = g * 4 + t;
    int q = p * 2 + hk;
    return ((((((size_t)tile * 2 + kc) * 4 + wcol) * 4 + j) * 8 + ks) * 32 + lane) * 8
           + q * 2 + e;
}

// ---- prep: blocks 0..511 softmax (16 rows each), 512..767 V convert -------
__global__ void __launch_bounds__(512, 1) prep_k(const float* __restrict__ S,
                                                 const float* __restrict__ V) {
    if (blockIdx.x < 512) {
        __shared__ __half sm[16 * SROW];
        int base = blockIdx.x * 16;
        int w = threadIdx.x >> 5, lane = threadIdx.x & 31;
        int row = base + w;
        const float4* Sr = reinterpret_cast<const float4*>(S + (size_t)row * DK);
        float4 v0 = Sr[lane * 2];
        float4 v1 = Sr[lane * 2 + 1];
        float e[8] = {v0.x, v0.y, v0.z, v0.w, v1.x, v1.y, v1.z, v1.w};
        float mx = e[0];
#pragma unroll
        for (int i = 1; i < 8; i++) mx = fmaxf(mx, e[i]);
#pragma unroll
        for (int o = 16; o; o >>= 1) mx = fmaxf(mx, __shfl_xor_sync(0xffffffffu, mx, o));
        float s = 0.0f;
#pragma unroll
        for (int i = 0; i < 8; i++) { e[i] = __expf(e[i] - mx); s += e[i]; }
#pragma unroll
        for (int o = 16; o; o >>= 1) s += __shfl_xor_sync(0xffffffffu, s, o);
        float inv = __frcp_rn(s);
        uint32_t h01 = h2u(__floats2half2_rn(e[0] * inv, e[1] * inv));
        uint32_t h23 = h2u(__floats2half2_rn(e[2] * inv, e[3] * inv));
        uint32_t h45 = h2u(__floats2half2_rn(e[4] * inv, e[5] * inv));
        uint32_t h67 = h2u(__floats2half2_rn(e[6] * inv, e[7] * inv));
        uint32_t sb = smem_u32(sm);
        asm volatile("st.shared.v4.b32 [%0], {%1,%2,%3,%4};"
                     :: "r"(sb + (uint32_t)(w * SROW + lane * 8) * 2),
                        "r"(h01), "r"(h23), "r"(h45), "r"(h67));
        __syncthreads();
        // phase 2: 512 chunks = kc2 x ks8 x lane32; one 16B v4 store each
        int c = threadIdx.x;
        int l = c & 31, ks = (c >> 5) & 7, kc = (c >> 8) & 1;
        int g = l >> 2, t4 = l & 3;
        int k0 = kc * 128 + ks * 16 + 2 * t4;
        const __half2* a0 = reinterpret_cast<const __half2*>(sm + g * SROW);
        const __half2* a8 = reinterpret_cast<const __half2*>(sm + (g + 8) * SROW);
        uint4 outv = make_uint4(h2u(a0[k0 >> 1]), h2u(a8[k0 >> 1]),
                                h2u(a0[(k0 >> 1) + 4]), h2u(a8[(k0 >> 1) + 4]));
        *reinterpret_cast<uint4*>(&g_Ph[idxA(base + g, k0)]) = outv;
    } else {
        // V convert: each thread builds TWO adjacent chunks from 4 float4
        // reads and 2 contiguous 16B stores. 131072 pair-units total.
        int u = (blockIdx.x - 512) * 512 + threadIdx.x;
        int t2 = u & 1, g = (u >> 1) & 7, ks = (u >> 4) & 7;
        int j = (u >> 7) & 3, wc = (u >> 9) & 3, kc = (u >> 11) & 1;
        int tile = u >> 12;
        int v0 = tile * 256 + wc * 64 + j * 16 + g;
        int kb = kc * 128 + ks * 16 + 4 * t2;
        const float4* Va = reinterpret_cast<const float4*>(V + (size_t)v0 * DK + kb);
        const float4* Vb =
            reinterpret_cast<const float4*>(V + (size_t)(v0 + 8) * DK + kb);
        float4 fa0 = Va[0];
        float4 fa8 = Va[2];
        float4 fb0 = Vb[0];
        float4 fb8 = Vb[2];
        uint4 c0 = make_uint4(h2u(__floats2half2_rn(fa0.x, fa0.y)),
                              h2u(__floats2half2_rn(fa8.x, fa8.y)),
                              h2u(__floats2half2_rn(fb0.x, fb0.y)),
                              h2u(__floats2half2_rn(fb8.x, fb8.y)));
        uint4 c1 = make_uint4(h2u(__floats2half2_rn(fa0.z, fa0.w)),
                              h2u(__floats2half2_rn(fa8.z, fa8.w)),
                              h2u(__floats2half2_rn(fb0.z, fb0.w)),
                              h2u(__floats2half2_rn(fb8.z, fb8.w)));
        uint4* dst = reinterpret_cast<uint4*>(&g_Vh[idxB(v0, kb)]);
        dst[0] = c0;
        dst[1] = c1;
    }
}

// ---------------- GEMM (mainloop at HW floor; + PDL grid-sync) --------------
__device__ __forceinline__ void load_stage(uint32_t sb, int s,
                                           const __half* Asrc, const __half* Bsrc,
                                           int kc, int tid) {
    uint32_t base = sb + s * STG_BYTES;
    const __half* Ak = Asrc + (size_t)kc * 16384; // 32 KB of halves
    const __half* Bk = Bsrc + (size_t)kc * 32768; // 64 KB of halves
#pragma unroll
    for (int it = 0; it < 8; it++) {
        int i = it * THREADS + tid;
        cp16(base + i * 16, Ak + i * 8);
    }
#pragma unroll
    for (int it = 0; it < 16; it++) {
        int i = it * THREADS + tid;
        cp16(base + A_BYTES + i * 16, Bk + i * 8);
    }
    asm volatile("cp.async.commit_group;" ::: "memory");
}

__global__ void __launch_bounds__(THREADS, 1)
gemm_k(float* __restrict__ out, int m) {
    extern __shared__ __half smh[];
    uint32_t sb = smem_u32(smh);
    int tid = threadIdx.x;
    int lane = tid & 31, warp = tid >> 5;
    int wrow = warp >> 2;  // 0..1 (x64 rows)
    int wcol = warp & 3;   // 0..3 (x64 cols)

    // PDL: wait for prep_k completion before first scratch read.
    cudaGridDependencySynchronize();

    int ltile = blockIdx.x, lkc = 0, gstage = 0;
    {
        const __half* Asrc = g_Ph + (size_t)(ltile >> 5) * (2 * 16384);
        const __half* Bsrc = g_Vh + (size_t)(ltile & 31) * (2 * 32768);
        load_stage(sb, gstage, Asrc, Bsrc, lkc, tid);
        gstage ^= 1;
        if (++lkc == 2) { lkc = 0; ltile += GRID_P; }
    }

    int cstage = 0;
#pragma unroll 1
    for (int tile = blockIdx.x; tile < NTILES; tile += GRID_P) {
        float acc[4][8][4];
#pragma unroll
        for (int i = 0; i < 4; i++)
#pragma unroll
            for (int j = 0; j < 8; j++)
#pragma unroll
                for (int r = 0; r < 4; r++) acc[i][j][r] = 0.0f;

#pragma unroll 1
        for (int k = 0; k < 2; k++) {
            asm volatile("cp.async.wait_group 0;" ::: "memory");
            __syncthreads();
            if (ltile < NTILES) {
                const __half* Asrc = g_Ph + (size_t)(ltile >> 5) * (2 * 16384);
                const __half* Bsrc = g_Vh + (size_t)(ltile & 31) * (2 * 32768);
                load_stage(sb, gstage, Asrc, Bsrc, lkc, tid);
            } else {
                asm volatile("cp.async.commit_group;" ::: "memory");
            }
            gstage ^= 1;
            if (++lkc == 2) { lkc = 0; ltile += GRID_P; }

            uint32_t stage = sb + cstage * STG_BYTES;
            uint32_t aW = stage + (uint32_t)wrow * 16384 + lane * 16;
            uint32_t bW = stage + A_BYTES + (uint32_t)wcol * 16384 + lane * 16;
#pragma unroll
            for (int ks = 0; ks < 8; ks++) {
                uint32_t a[4][4], b[4][4];
#pragma unroll
                for (int mt = 0; mt < 4; mt++)
                    lds128(a[mt], aW + (uint32_t)(mt * 8 + ks) * 512);
#pragma unroll
                for (int j = 0; j < 4; j++)
                    lds128(b[j], bW + (uint32_t)(j * 8 + ks) * 512);
#pragma unroll
                for (int mt = 0; mt < 4; mt++)
#pragma unroll
                    for (int j = 0; j < 4; j++) {
                        mma_fp16(acc[mt][2 * j], a[mt], b[j][0], b[j][1]);
                        mma_fp16(acc[mt][2 * j + 1], a[mt], b[j][2], b[j][3]);
                    }
            }
            cstage ^= 1;
        }

        size_t orow0 = (size_t)(tile >> 5) * BM + wrow * 64;
        size_t ocol0 = (size_t)(tile & 31) * BN + wcol * 64;
#pragma unroll
        for (int mt = 0; mt < 4; mt++) {
#pragma unroll
            for (int nt = 0; nt < 8; nt++) {
                size_t r = orow0 + mt * 16 + (lane >> 2);
                size_t c = ocol0 + nt * 8 + (lane & 3) * 2;
                float2 v0 = make_float2(acc[mt][nt][0], acc[mt][nt][1]);
                float2 v1 = make_float2(acc[mt][nt][2], acc[mt][nt][3]);
                *reinterpret_cast<float2*>(out + r * (size_t)m + c) = v0;
                *reinterpret_cast<float2*>(out + (r + 8) * (size_t)m + c) = v1;
            }
        }
    }
}

extern "C" void kernel_launch(void* const* d_in, const int* in_sizes, int n_in,
                              void* d_out, int out_size) {
    const float* S = (const float*)d_in[0];
    const float* V = (const float*)d_in[1];
    float* out = (float*)d_out;
    int m = in_sizes[1] / DK;  // 8192 V rows

    prep_k<<<768, 512>>>(S, V);

    cudaFuncSetAttribute(gemm_k, cudaFuncAttributeMaxDynamicSharedMemorySize,
                         SMEM_TOTAL);

    // PDL launch: gemm may begin (prologue) while prep_k drains; the device
    // grid-sync above blocks its scratch reads until prep_k completes.
    cudaLaunchAttribute attrs[1];
    attrs[0].id = cudaLaunchAttributeProgrammaticStreamSerialization;
    attrs[0].val.programmaticStreamSerializationAllowed = 1;
    cudaLaunchConfig_t cfg = {};
    cfg.gridDim = dim3(GRID_P, 1, 1);
    cfg.blockDim = dim3(THREADS, 1, 1);
    cfg.dynamicSmemBytes = SMEM_TOTAL;
    cfg.stream = 0;
    cfg.attrs = attrs;
    cfg.numAttrs = 1;
    cudaError_t err = cudaLaunchKernelEx(&cfg, gemm_k, out, m);
    if (err != cudaSuccess) {
        // Fallback: plain launch (stream-ordered after prep_k).
        gemm_k<<<GRID_P, THREADS, SMEM_TOTAL>>>(out, m);
    }
}